// round 2
// baseline (speedup 1.0000x reference)
#include <cuda_runtime.h>
#include <math.h>
#include <stdint.h>

#define BSZ 131072
#define TTR 10
#define KF 304          // padded feature dim (300 -> 304, zeros)
#define HID 1024
#define NUM_ELEM 118
#define EMB 10

// ---- scratch (device globals; no runtime allocation) ----
__device__ float g_feat[(size_t)BSZ * KF];   // features, padded to 304
__device__ float g_h1[(size_t)BSZ * HID];    // layer-1 output (post relu)
__device__ float g_w1p[(size_t)KF * HID];    // W1 zero-padded to 304 rows

// ---- helpers ----
__device__ __forceinline__ uint32_t f2tf(float x) {
    uint32_t r;
    asm("cvt.rna.tf32.f32 %0, %1;" : "=r"(r) : "f"(x));
    return r;
}

__device__ __forceinline__ void mma8(float* c, const uint32_t* a,
                                     uint32_t b0, uint32_t b1) {
    asm volatile(
        "mma.sync.aligned.m16n8k8.row.col.f32.tf32.tf32.f32 "
        "{%0,%1,%2,%3}, {%4,%5,%6,%7}, {%8,%9}, {%0,%1,%2,%3};"
        : "+f"(c[0]), "+f"(c[1]), "+f"(c[2]), "+f"(c[3])
        : "r"(a[0]), "r"(a[1]), "r"(a[2]), "r"(a[3]), "r"(b0), "r"(b1));
}

__device__ __forceinline__ void cp16(float* dst, const float* src) {
    uint32_t d = (uint32_t)__cvta_generic_to_shared(dst);
    asm volatile("cp.async.ca.shared.global [%0], [%1], 16;" :: "r"(d), "l"(src));
}
#define CP_COMMIT() asm volatile("cp.async.commit_group;")
#define CP_WAIT1()  asm volatile("cp.async.wait_group 1;")
#define CP_WAIT0()  asm volatile("cp.async.wait_group 0;")

// ---- kernel: pad W1 to 304 rows ----
__global__ void pad_w1_kernel(const float* __restrict__ W1, float* __restrict__ w1p) {
    int i = blockIdx.x * blockDim.x + threadIdx.x;
    if (i >= KF * HID) return;
    int row = i >> 10;
    w1p[i] = (row < 300) ? W1[i] : 0.0f;
}

// ---- kernel: init output with b3 ----
__global__ void init_out_kernel(float* __restrict__ out, const float* __restrict__ b3) {
    int i = blockIdx.x * blockDim.x + threadIdx.x;
    if (i < BSZ) out[i] = b3[0];
}

// ---- kernel: build features [B, 304] ----
__global__ void feat_kernel(const float* __restrict__ structures,
                            const float* __restrict__ E,
                            float* __restrict__ feat) {
    __shared__ float sE[NUM_ELEM * EMB];
    for (int i = threadIdx.x; i < NUM_ELEM * EMB; i += blockDim.x) sE[i] = E[i];
    __syncthreads();

    int gidx = blockIdx.x * blockDim.x + threadIdx.x;   // one per (b, t)
    if (gidx >= BSZ * TTR) return;
    int b = gidx / TTR;
    int t = gidx % TTR;

    const float* s = structures + ((size_t)b * TTR + t) * 3;
    int ii = (int)s[0];
    int jj = (int)s[1];
    float d = s[2];
    bool mi = (ii != 0);
    bool mj = (jj != 0);

    float* o = feat + (size_t)b * KF + t * 30;
    #pragma unroll
    for (int c = 0; c < 10; c++) o[c] = mi ? sE[ii * EMB + c] : 0.0f;
    #pragma unroll
    for (int c = 0; c < 10; c++) o[10 + c] = mj ? sE[jj * EMB + c] : 0.0f;
    #pragma unroll
    for (int c = 0; c < 10; c++) {
        float diff = 0.7f * (float)(c + 1) - d;
        o[20 + c] = mi ? expf(-diff * diff) : 0.0f;
    }
    if (t == 0) {  // zero the 4 padding columns
        float* p = feat + (size_t)b * KF + 300;
        p[0] = 0.0f; p[1] = 0.0f; p[2] = 0.0f; p[3] = 0.0f;
    }
}

// ---- fused GEMM: C = relu(A@B + bias); EPI=0 stores [*,1024]; EPI=1 fuses W3 dot ----
#define BM 128
#define BN 256
#define BK 16
#define ASTR 20     // As row stride in floats (conflict-free pad)
#define BSTR 264    // Bs row stride in floats (conflict-free pad)
#define SMEM_BYTES ((2*BM*ASTR + 2*BK*BSTR + 2*BN) * 4)

template <int EPI>
__global__ void __launch_bounds__(256, 1) gemm_kernel(
    const float* __restrict__ A, int lda, int K,
    const float* __restrict__ Bw,     // [K, 1024] row-major
    const float* __restrict__ bias,   // [1024]
    const float* __restrict__ W3,     // [1024] (EPI==1)
    float* __restrict__ Cout)         // h1 (EPI==0) or out[B] (EPI==1)
{
    extern __shared__ float smem[];
    float* As    = smem;                      // [2][BM][ASTR]
    float* Bs    = smem + 2 * BM * ASTR;      // [2][BK][BSTR]
    float* sBias = Bs + 2 * BK * BSTR;        // [BN]
    float* sW3   = sBias + BN;                // [BN]

    const int tid  = threadIdx.x;
    const int lane = tid & 31;
    const int wid  = tid >> 5;
    const int wm   = wid & 3;       // 4 warp rows of 32
    const int wn   = wid >> 2;      // 2 warp cols of 128
    const int g    = lane >> 2;     // groupID
    const int t    = lane & 3;      // threadID_in_group
    const int m0   = blockIdx.y * BM;
    const int n0   = blockIdx.x * BN;

    float acc[2][16][4];
    #pragma unroll
    for (int i = 0; i < 2; i++)
        #pragma unroll
        for (int j = 0; j < 16; j++)
            #pragma unroll
            for (int k = 0; k < 4; k++) acc[i][j][k] = 0.0f;

    const int KT = K / BK;

    auto issue = [&](int kt, int buf) {
        int k0 = kt * BK;
        #pragma unroll
        for (int i = 0; i < 2; i++) {               // A tile: 512 x 16B
            int l = tid + i * 256;
            int row = l >> 2, kv = l & 3;
            cp16(&As[buf * BM * ASTR + row * ASTR + kv * 4],
                 A + (size_t)(m0 + row) * lda + k0 + kv * 4);
        }
        #pragma unroll
        for (int i = 0; i < 4; i++) {               // B tile: 1024 x 16B
            int l = tid + i * 256;
            int row = l >> 6, c4 = l & 63;
            cp16(&Bs[buf * BK * BSTR + row * BSTR + c4 * 4],
                 Bw + (size_t)(k0 + row) * HID + n0 + c4 * 4);
        }
    };

    auto compute = [&](int buf) {
        const float* Ab = &As[buf * BM * ASTR];
        const float* Bb = &Bs[buf * BK * BSTR];
        #pragma unroll
        for (int ks = 0; ks < BK; ks += 8) {
            uint32_t a[2][4];
            #pragma unroll
            for (int ms = 0; ms < 2; ms++) {
                int r = wm * 32 + ms * 16;
                a[ms][0] = f2tf(Ab[(r + g)     * ASTR + ks + t]);
                a[ms][1] = f2tf(Ab[(r + g + 8) * ASTR + ks + t]);
                a[ms][2] = f2tf(Ab[(r + g)     * ASTR + ks + t + 4]);
                a[ms][3] = f2tf(Ab[(r + g + 8) * ASTR + ks + t + 4]);
            }
            #pragma unroll
            for (int ns = 0; ns < 16; ns++) {
                int c = wn * 128 + ns * 8 + g;
                uint32_t b0 = f2tf(Bb[(ks + t)     * BSTR + c]);
                uint32_t b1 = f2tf(Bb[(ks + t + 4) * BSTR + c]);
                mma8(acc[0][ns], a[0], b0, b1);
                mma8(acc[1][ns], a[1], b0, b1);
            }
        }
    };

    issue(0, 0);
    CP_COMMIT();
    for (int kt = 0; kt < KT; kt++) {
        int cur = kt & 1;
        if (kt + 1 < KT) { issue(kt + 1, cur ^ 1); CP_COMMIT(); CP_WAIT1(); }
        else             { CP_WAIT0(); }
        __syncthreads();
        compute(cur);
        __syncthreads();
    }

    // epilogue
    for (int i = tid; i < BN; i += 256) {
        sBias[i] = bias[n0 + i];
        if (EPI == 1) sW3[i] = W3[n0 + i];
    }
    __syncthreads();

    if (EPI == 0) {
        #pragma unroll
        for (int ms = 0; ms < 2; ms++) {
            int row = m0 + wm * 32 + ms * 16 + g;
            #pragma unroll
            for (int ns = 0; ns < 16; ns++) {
                int cl  = wn * 128 + ns * 8 + t * 2;
                int col = n0 + cl;
                float2 v0, v1;
                v0.x = fmaxf(acc[ms][ns][0] + sBias[cl],     0.0f);
                v0.y = fmaxf(acc[ms][ns][1] + sBias[cl + 1], 0.0f);
                v1.x = fmaxf(acc[ms][ns][2] + sBias[cl],     0.0f);
                v1.y = fmaxf(acc[ms][ns][3] + sBias[cl + 1], 0.0f);
                *(float2*)&Cout[(size_t)row * HID + col]       = v0;
                *(float2*)&Cout[(size_t)(row + 8) * HID + col] = v1;
            }
        }
    } else {
        float racc[2][2] = {{0.0f, 0.0f}, {0.0f, 0.0f}};
        #pragma unroll
        for (int ms = 0; ms < 2; ms++) {
            #pragma unroll
            for (int ns = 0; ns < 16; ns++) {
                int cl = wn * 128 + ns * 8 + t * 2;
                racc[ms][0] += fmaxf(acc[ms][ns][0] + sBias[cl],     0.0f) * sW3[cl]
                             + fmaxf(acc[ms][ns][1] + sBias[cl + 1], 0.0f) * sW3[cl + 1];
                racc[ms][1] += fmaxf(acc[ms][ns][2] + sBias[cl],     0.0f) * sW3[cl]
                             + fmaxf(acc[ms][ns][3] + sBias[cl + 1], 0.0f) * sW3[cl + 1];
            }
        }
        #pragma unroll
        for (int ms = 0; ms < 2; ms++) {
            #pragma unroll
            for (int rp = 0; rp < 2; rp++) {
                float p = racc[ms][rp];
                p += __shfl_xor_sync(0xffffffffu, p, 1);
                p += __shfl_xor_sync(0xffffffffu, p, 2);
                if (t == 0)
                    atomicAdd(&Cout[m0 + wm * 32 + ms * 16 + rp * 8 + g], p);
            }
        }
    }
}

// ---- launch ----
extern "C" void kernel_launch(void* const* d_in, const int* in_sizes, int n_in,
                              void* d_out, int out_size) {
    const float* structures = (const float*)d_in[0];
    const float* E  = (const float*)d_in[1];
    const float* W1 = (const float*)d_in[2];
    const float* b1 = (const float*)d_in[3];
    const float* W2 = (const float*)d_in[4];
    const float* b2 = (const float*)d_in[5];
    const float* W3 = (const float*)d_in[6];
    const float* b3 = (const float*)d_in[7];
    float* out = (float*)d_out;

    float *feat, *h1, *w1p;
    cudaGetSymbolAddress((void**)&feat, g_feat);
    cudaGetSymbolAddress((void**)&h1,   g_h1);
    cudaGetSymbolAddress((void**)&w1p,  g_w1p);

    cudaFuncSetAttribute(gemm_kernel<0>, cudaFuncAttributeMaxDynamicSharedMemorySize, SMEM_BYTES);
    cudaFuncSetAttribute(gemm_kernel<1>, cudaFuncAttributeMaxDynamicSharedMemorySize, SMEM_BYTES);

    pad_w1_kernel<<<(KF * HID + 255) / 256, 256>>>(W1, w1p);
    init_out_kernel<<<(BSZ + 255) / 256, 256>>>(out, b3);
    feat_kernel<<<(BSZ * TTR + 255) / 256, 256>>>(structures, E, feat);

    dim3 grid(HID / BN, BSZ / BM);  // (4, 1024)
    gemm_kernel<0><<<grid, 256, SMEM_BYTES>>>(feat, KF, KF, w1p, b1, nullptr, h1);
    gemm_kernel<1><<<grid, 256, SMEM_BYTES>>>(h1, HID, HID, W2, b2, W3, out);
}